// round 9
// baseline (speedup 1.0000x reference)
#include <cuda_runtime.h>
#include <cuda_bf16.h>
#include <cuda_fp16.h>
#include <math.h>

// Problem constants (shapes are fixed for this problem instance)
#define NN      100000
#define NE      3200000
#define FIN     512
#define HID     64
#define NCLS    47
#define KHOPS   10
#define ALPHA   0.1f

// -------- device scratch (no allocations allowed) --------
__device__ int   g_count[NN];        // in-degree counts (real edges only)
__device__ int   g_colptr[NN + 1];   // CSR row pointers (by destination)
__device__ int   g_cursor[NN];       // scatter cursors
__device__ float g_dis[NN];          // D^-1/2 (deg incl. self loop)
__device__ int   g_incl[NN];         // inclusive per-block scan temp
__device__ int   g_blksum[256];      // block sums for scan
__device__ __align__(16) int g_edge[NE + 8];  // src index, sorted by dst (+pad)
__device__ __half g_Wt[(size_t)HID * FIN];                // W^T fp16 [64][512]
__device__ __align__(256) __half2 g_h0h[(size_t)NN * 32]; // fp16 anchor (unscaled h0)
__device__ __align__(256) float g_hF[(size_t)NN * HID];   // final fp32 h
__device__ __align__(256) __half2 g_hsA[(size_t)NN * 32]; // scaled fp16 state
__device__ __align__(256) __half2 g_hsB[(size_t)NN * 32];

// ---------------- cp.async helpers ----------------
__device__ __forceinline__ void cp16(void* smem, const void* gmem) {
    unsigned s = (unsigned)__cvta_generic_to_shared(smem);
    asm volatile("cp.async.ca.shared.global [%0], [%1], 16;\n" :: "r"(s), "l"(gmem));
}
__device__ __forceinline__ void cp_commit() {
    asm volatile("cp.async.commit_group;\n");
}
template <int N>
__device__ __forceinline__ void cp_wait() {
    asm volatile("cp.async.wait_group %0;\n" :: "n"(N));
}

// ---------------- CSR build ----------------
__global__ void k_hist(const int* __restrict__ col, int e) {
    int i4 = (blockIdx.x * blockDim.x + threadIdx.x) * 4;
    if (i4 + 4 <= e) {
        int4 c = *(const int4*)(col + i4);
        atomicAdd(&g_count[c.x], 1);
        atomicAdd(&g_count[c.y], 1);
        atomicAdd(&g_count[c.z], 1);
        atomicAdd(&g_count[c.w], 1);
    } else {
        for (int i = i4; i < e; i++) atomicAdd(&g_count[col[i]], 1);
    }
}

// Hillis-Steele block scan (1024/block); also computes g_dis
__global__ void k_scan_block(int n) {
    __shared__ int s[1024];
    int i = blockIdx.x * 1024 + threadIdx.x;
    int v = (i < n) ? g_count[i] : 0;
    if (i < n) g_dis[i] = rsqrtf((float)(v + 1));  // +1 self loop
    s[threadIdx.x] = v;
    __syncthreads();
    #pragma unroll
    for (int off = 1; off < 1024; off <<= 1) {
        int t = (threadIdx.x >= off) ? s[threadIdx.x - off] : 0;
        __syncthreads();
        s[threadIdx.x] += t;
        __syncthreads();
    }
    if (i < n) g_incl[i] = s[threadIdx.x];
    if (threadIdx.x == 1023) g_blksum[blockIdx.x] = s[1023];
}

__global__ void k_scan_sums(int nb) {
    if (blockIdx.x == 0 && threadIdx.x == 0) {
        int acc = 0;
        for (int b = 0; b < nb; b++) { int t = g_blksum[b]; g_blksum[b] = acc; acc += t; }
    }
}

__global__ void k_finalize(int n) {
    int i = blockIdx.x * blockDim.x + threadIdx.x;
    if (i == 0) g_colptr[0] = 0;
    if (i < n) {
        int e = g_incl[i] + g_blksum[i >> 10];
        g_colptr[i + 1] = e;
        g_cursor[i] = e - g_count[i];
    }
}

__global__ void k_scatter_edges(const int* __restrict__ row, const int* __restrict__ col, int e) {
    int i = blockIdx.x * blockDim.x + threadIdx.x;
    if (i >= e) return;
    int c = col[i];
    int pos = atomicAdd(&g_cursor[c], 1);
    g_edge[pos] = row[i];
}

// ---------------- W preconvert: g_Wt[n][k] = (half)W[k][n] ----------------
__global__ void k_wconv(const float* __restrict__ W) {
    int i = blockIdx.x * blockDim.x + threadIdx.x;
    if (i < FIN * HID) {
        int k = i >> 6, nn = i & 63;
        g_Wt[(size_t)nn * FIN + k] = __float2half(W[(size_t)k * HID + nn]);
    }
}

// ---------------- Embed GEMM via tensor cores, fp32-X cp.async double-buffered ----
// H0 = relu(X @ W + b). X read fp32 directly, converted in the fragment path
// with round-to-nearest (bit-identical to the previous preconvert pass).
#define KC 32
#define XFSTR 40           // fp32 X smem row stride (floats): conflict-free LDS.64
#define WSTR  40           // fp16 W smem row stride (halves)
#define NCHUNK (FIN / KC)  // 16
__global__ __launch_bounds__(256) void k_embed_mma(const float* __restrict__ X,
                                                   const float* __restrict__ b, int n) {
    __shared__ __align__(16) float  Xs[2][128][XFSTR];  // 41 KB
    __shared__ __align__(16) __half Ws[2][64][WSTR];    // 10 KB
    __shared__ float bs[HID];
    int tid = threadIdx.x;
    int wid = tid >> 5, lane = tid & 31;
    int g  = lane >> 2;          // 0..7
    int cq = (lane & 3) * 2;     // 0,2,4,6
    int rowBase = blockIdx.x * 128;
    if (tid < HID) bs[tid] = b[tid];

    // X: 2 threads/row, each thread 16 consecutive floats (4 x cp16)
    int xr = tid >> 1;
    int xp = (tid & 1) * 16;     // float offset
    int gxr = rowBase + xr;
    if (gxr >= n) gxr = n - 1;   // clamp (epilogue guards writes)
    const float* xsrc = X + (size_t)gxr * FIN + xp;
    // W: 4 threads/row, each 8 halves (1 x cp16)
    int wr = tid >> 2;
    int wq = (tid & 3) * 8;
    const __half* wsrc = g_Wt + (size_t)wr * FIN + wq;

    float acc[8][4];
    #pragma unroll
    for (int i = 0; i < 8; i++)
        #pragma unroll
        for (int j = 0; j < 4; j++) acc[i][j] = 0.f;

    // prologue: chunk 0 -> stage 0
    #pragma unroll
    for (int t = 0; t < 4; t++)
        cp16(&Xs[0][xr][xp + t * 4], xsrc + t * 4);
    cp16(&Ws[0][wr][wq], wsrc);
    cp_commit();

    for (int c = 0; c < NCHUNK; c++) {
        int st = c & 1;
        if (c + 1 < NCHUNK) {
            int ns = (c + 1) & 1;
            int k0 = (c + 1) * KC;
            #pragma unroll
            for (int t = 0; t < 4; t++)
                cp16(&Xs[ns][xr][xp + t * 4], xsrc + k0 + t * 4);
            cp16(&Ws[ns][wr][wq], wsrc + k0);
            cp_commit();
            cp_wait<1>();
        } else {
            cp_wait<0>();
        }
        __syncthreads();

        #pragma unroll
        for (int kk = 0; kk < KC; kk += 16) {
            float2 x0 = *(const float2*)&Xs[st][wid * 16 + g][kk + cq];
            float2 x1 = *(const float2*)&Xs[st][wid * 16 + g + 8][kk + cq];
            float2 x2 = *(const float2*)&Xs[st][wid * 16 + g][kk + cq + 8];
            float2 x3 = *(const float2*)&Xs[st][wid * 16 + g + 8][kk + cq + 8];
            __half2 h0 = __floats2half2_rn(x0.x, x0.y);
            __half2 h1 = __floats2half2_rn(x1.x, x1.y);
            __half2 h2 = __floats2half2_rn(x2.x, x2.y);
            __half2 h3 = __floats2half2_rn(x3.x, x3.y);
            unsigned a0 = *(unsigned*)&h0;
            unsigned a1 = *(unsigned*)&h1;
            unsigned a2 = *(unsigned*)&h2;
            unsigned a3 = *(unsigned*)&h3;
            #pragma unroll
            for (int cb = 0; cb < 8; cb++) {
                unsigned b0 = *(const unsigned*)&Ws[st][cb * 8 + g][kk + cq];
                unsigned b1 = *(const unsigned*)&Ws[st][cb * 8 + g][kk + cq + 8];
                asm volatile(
                    "mma.sync.aligned.m16n8k16.row.col.f32.f16.f16.f32 "
                    "{%0,%1,%2,%3}, {%4,%5,%6,%7}, {%8,%9}, {%0,%1,%2,%3};"
                    : "+f"(acc[cb][0]), "+f"(acc[cb][1]),
                      "+f"(acc[cb][2]), "+f"(acc[cb][3])
                    : "r"(a0), "r"(a1), "r"(a2), "r"(a3), "r"(b0), "r"(b1));
            }
        }
        __syncthreads();
    }

    // epilogue: bias + relu -> fp16 anchor g_h0h and dis-scaled fp16 state g_hsA
    int r0 = rowBase + wid * 16 + g;
    int r1 = r0 + 8;
    float d0 = (r0 < n) ? g_dis[r0] : 0.f;
    float d1 = (r1 < n) ? g_dis[r1] : 0.f;
    #pragma unroll
    for (int cb = 0; cb < 8; cb++) {
        int c = cb * 8 + cq;
        float bx = bs[c], by = bs[c + 1];
        if (r0 < n) {
            float v0 = fmaxf(acc[cb][0] + bx, 0.f);
            float v1 = fmaxf(acc[cb][1] + by, 0.f);
            g_h0h[(size_t)r0 * 32 + (c >> 1)] = __floats2half2_rn(v0, v1);
            g_hsA[(size_t)r0 * 32 + (c >> 1)] = __floats2half2_rn(d0 * v0, d0 * v1);
        }
        if (r1 < n) {
            float v0 = fmaxf(acc[cb][2] + bx, 0.f);
            float v1 = fmaxf(acc[cb][3] + by, 0.f);
            g_h0h[(size_t)r1 * 32 + (c >> 1)] = __floats2half2_rn(v0, v1);
            g_hsA[(size_t)r1 * 32 + (c >> 1)] = __floats2half2_rn(d1 * v0, d1 * v1);
        }
    }
}

// ---------------- Propagation hop: quarter-warp uint4 gathers ----------------
// hs row = 8 uint4 (64 fp16). Quarter q (8 lanes) handles edge e+q; each lane
// owns 8 features. One LDG.128 per lane covers the full 128B row of one edge.
__device__ __forceinline__ void acc8(float* a, uint4 v) {
    float2 f0 = __half22float2(*(__half2*)&v.x);
    float2 f1 = __half22float2(*(__half2*)&v.y);
    float2 f2 = __half22float2(*(__half2*)&v.z);
    float2 f3 = __half22float2(*(__half2*)&v.w);
    a[0] += f0.x; a[1] += f0.y; a[2] += f1.x; a[3] += f1.y;
    a[4] += f2.x; a[5] += f2.y; a[6] += f3.x; a[7] += f3.y;
}

__global__ __launch_bounds__(256) void k_hop(const uint4* __restrict__ hs,
                                             uint4* __restrict__ hn,
                                             int n, int final_hop) {
    int warp = (blockIdx.x * blockDim.x + threadIdx.x) >> 5;
    int lane = threadIdx.x & 31;
    if (warp >= n) return;
    int q   = lane >> 3;       // quarter 0..3
    int sub = lane & 7;        // uint4 slot (8 features)
    int beg = g_colptr[warp], end = g_colptr[warp + 1];

    float a[8] = {0.f, 0.f, 0.f, 0.f, 0.f, 0.f, 0.f, 0.f};
    float bb[8] = {0.f, 0.f, 0.f, 0.f, 0.f, 0.f, 0.f, 0.f};
    if (q == 0) {              // self loop counted once
        uint4 s = hs[(size_t)warp * 8 + sub];
        acc8(a, s);
    }

    int e = beg;
    for (; e + 8 <= end; e += 8) {     // 2 groups of 4 edges
        int i0 = __ldg(&g_edge[e + q]);
        int i1 = __ldg(&g_edge[e + 4 + q]);
        uint4 v0 = hs[(size_t)i0 * 8 + sub];
        uint4 v1 = hs[(size_t)i1 * 8 + sub];
        acc8(a, v0);
        acc8(bb, v1);
    }
    for (; e < end; e += 4) {          // tail groups (predicated)
        bool valid = (e + q) < end;
        int i0 = valid ? __ldg(&g_edge[e + q]) : 0;
        uint4 v0 = hs[(size_t)i0 * 8 + sub];
        if (valid) acc8(a, v0);
    }
    #pragma unroll
    for (int i = 0; i < 8; i++) a[i] += bb[i];
    #pragma unroll
    for (int i = 0; i < 8; i++) {
        a[i] += __shfl_xor_sync(0xffffffffu, a[i], 8);
        a[i] += __shfl_xor_sync(0xffffffffu, a[i], 16);
    }

    float d = g_dis[warp];
    if (q == 0) {
        uint4 hz = ((const uint4*)g_h0h)[(size_t)warp * 8 + sub];
        float2 z0 = __half22float2(*(__half2*)&hz.x);
        float2 z1 = __half22float2(*(__half2*)&hz.y);
        float2 z2 = __half22float2(*(__half2*)&hz.z);
        float2 z3 = __half22float2(*(__half2*)&hz.w);
        float o0 = 0.9f * d * a[0] + 0.1f * z0.x;
        float o1 = 0.9f * d * a[1] + 0.1f * z0.y;
        float o2 = 0.9f * d * a[2] + 0.1f * z1.x;
        float o3 = 0.9f * d * a[3] + 0.1f * z1.y;
        float o4 = 0.9f * d * a[4] + 0.1f * z2.x;
        float o5 = 0.9f * d * a[5] + 0.1f * z2.y;
        float o6 = 0.9f * d * a[6] + 0.1f * z3.x;
        float o7 = 0.9f * d * a[7] + 0.1f * z3.y;
        if (final_hop) {
            float* dst = g_hF + (size_t)warp * HID + sub * 8;
            *(float4*)(dst)     = make_float4(o0, o1, o2, o3);
            *(float4*)(dst + 4) = make_float4(o4, o5, o6, o7);
        } else {
            __half2 p0 = __floats2half2_rn(d * o0, d * o1);
            __half2 p1 = __floats2half2_rn(d * o2, d * o3);
            __half2 p2 = __floats2half2_rn(d * o4, d * o5);
            __half2 p3 = __floats2half2_rn(d * o6, d * o7);
            uint4 w;
            w.x = *(unsigned*)&p0; w.y = *(unsigned*)&p1;
            w.z = *(unsigned*)&p2; w.w = *(unsigned*)&p3;
            hn[(size_t)warp * 8 + sub] = w;
        }
    }
}

// ---------------- Predict + softmax family ----------------
__global__ __launch_bounds__(256) void k_pred(const float* __restrict__ h,
                                              const float* __restrict__ Wp,
                                              const float* __restrict__ bp,
                                              float* __restrict__ out,
                                              int n, int out_size) {
    __shared__ float Ws[HID * NCLS];
    __shared__ float bs[NCLS];
    __shared__ float hsm[8][HID];
    for (int i = threadIdx.x; i < HID * NCLS; i += blockDim.x) Ws[i] = Wp[i];
    if (threadIdx.x < NCLS) bs[threadIdx.x] = bp[threadIdx.x];
    __syncthreads();

    int warp = threadIdx.x >> 5;
    int lane = threadIdx.x & 31;
    int v = blockIdx.x * 8 + warp;
    if (v >= n) return;

    hsm[warp][lane]      = h[(size_t)v * HID + lane];
    hsm[warp][lane + 32] = h[(size_t)v * HID + lane + 32];
    __syncwarp();

    int c1 = (lane + 32 < NCLS) ? (lane + 32) : (NCLS - 1);
    float a0 = bs[lane];
    float a1 = bs[c1];
    #pragma unroll
    for (int k = 0; k < HID; k++) {
        float hk = hsm[warp][k];
        a0 += hk * Ws[k * NCLS + lane];
        a1 += hk * Ws[k * NCLS + c1];
    }
    bool l1 = (lane + 32 < NCLS);

    float m = fmaxf(a0, l1 ? a1 : -INFINITY);
    #pragma unroll
    for (int o = 16; o > 0; o >>= 1) m = fmaxf(m, __shfl_xor_sync(0xffffffff, m, o));
    float e0 = __expf(a0 - m);
    float e1 = l1 ? __expf(a1 - m) : 0.f;
    float s = e0 + e1;
    #pragma unroll
    for (int o = 16; o > 0; o >>= 1) s += __shfl_xor_sync(0xffffffff, s, o);
    float lse = m + logf(s);
    float inv = 1.f / s;

    size_t base = (size_t)v * NCLS;
    size_t sec  = (size_t)n * NCLS;
    out[base + lane] = a0 - lse;
    if (l1) out[base + lane + 32] = a1 - lse;
    if (out_size >= 2 * (int)sec) {
        out[sec + base + lane] = a0;
        if (l1) out[sec + base + lane + 32] = a1;
    }
    if (out_size >= 3 * (int)sec) {
        out[2 * sec + base + lane] = e0 * inv;
        if (l1) out[2 * sec + base + lane + 32] = e1 * inv;
    }
}

// ---------------- launch ----------------
extern "C" void kernel_launch(void* const* d_in, const int* in_sizes, int n_in,
                              void* d_out, int out_size) {
    const float* x     = (const float*)d_in[0];   // [N,512]
    const int*   eidx  = (const int*)d_in[1];     // [2,E]
    const float* Wemb  = (const float*)d_in[2];   // [512,64]
    const float* bemb  = (const float*)d_in[3];   // [64]
    const float* Wpred = (const float*)d_in[4];   // [64,47]
    const float* bpred = (const float*)d_in[5];   // [47]
    float* out = (float*)d_out;

    int n = in_sizes[0] / FIN;
    int e = in_sizes[1] / 2;
    const int* row = eidx;       // source
    const int* col = eidx + e;   // target

    int nbE  = (e + 255) / 256;
    int nbE4 = (e / 4 + 255) / 256 + 1;
    int nbS  = (n + 1023) / 1024;

    cudaStream_t s2;
    cudaStreamCreate(&s2);
    cudaEvent_t evFork, evDis, evEmb;
    cudaEventCreateWithFlags(&evFork, cudaEventDisableTiming);
    cudaEventCreateWithFlags(&evDis,  cudaEventDisableTiming);
    cudaEventCreateWithFlags(&evEmb,  cudaEventDisableTiming);
    cudaStream_t s0 = (cudaStream_t)0;

    // fork: side stream converts W (depends only on inputs)
    cudaEventRecord(evFork, s0);
    cudaStreamWaitEvent(s2, evFork, 0);
    k_wconv<<<(FIN * HID + 255) / 256, 256, 0, s2>>>(Wemb);

    // main: degree histogram + scan (produces g_dis)
    {
        void* cntp; cudaGetSymbolAddress(&cntp, g_count);
        cudaMemsetAsync(cntp, 0, (size_t)n * sizeof(int), s0);
    }
    k_hist<<<nbE4, 256>>>(col, e);
    k_scan_block<<<nbS, 1024>>>(n);   // also computes g_dis
    cudaEventRecord(evDis, s0);

    // side: embed GEMM (needs g_dis + converted W; reads X fp32 directly)
    cudaStreamWaitEvent(s2, evDis, 0);
    k_embed_mma<<<(n + 127) / 128, 256, 0, s2>>>(x, bemb, n);
    cudaEventRecord(evEmb, s2);

    // main (overlapping with embed): finish CSR build
    k_scan_sums<<<1, 32>>>(nbS);
    k_finalize<<<nbS, 1024>>>(n);
    k_scatter_edges<<<nbE, 256>>>(row, col, e);

    // join
    cudaStreamWaitEvent(s0, evEmb, 0);

    // --- 10 propagation hops (ping-pong fp16 scaled state) ---
    int hopBlocks = (n * 32 + 255) / 256;
    {
        uint4* hAp; cudaGetSymbolAddress((void**)&hAp, g_hsA);
        uint4* hBp; cudaGetSymbolAddress((void**)&hBp, g_hsB);
        uint4* cur = hAp;
        for (int i = 0; i < KHOPS; i++) {
            int fin = (i == KHOPS - 1);
            uint4* dst = (cur == hAp) ? hBp : hAp;
            k_hop<<<hopBlocks, 256>>>(cur, dst, n, fin);
            cur = dst;
        }
    }

    // --- predict + softmax family (reads fp32 g_hF) ---
    float* hFp; cudaGetSymbolAddress((void**)&hFp, g_hF);
    k_pred<<<(n + 7) / 8, 256>>>(hFp, Wpred, bpred, out, n, out_size);
}

// round 10
// speedup vs baseline: 1.1363x; 1.1363x over previous
#include <cuda_runtime.h>
#include <cuda_bf16.h>
#include <cuda_fp16.h>
#include <math.h>

// Problem constants (shapes are fixed for this problem instance)
#define NN      100000
#define NE      3200000
#define FIN     512
#define HID     64
#define NCLS    47
#define KHOPS   10
#define ALPHA   0.1f

// -------- device scratch (no allocations allowed) --------
__device__ int   g_count[NN];        // in-degree counts (real edges only)
__device__ int   g_colptr[NN + 1];   // CSR row pointers (by destination)
__device__ int   g_cursor[NN];       // scatter cursors
__device__ float g_dis[NN];          // D^-1/2 (deg incl. self loop)
__device__ int   g_incl[NN];         // inclusive per-block scan temp
__device__ int   g_blksum[256];      // block sums for scan
__device__ __align__(16) int g_edge[NE + 8];  // src index, sorted by dst (+pad)
__device__ __half g_Wt[(size_t)HID * FIN];                // W^T fp16 [64][512]
__device__ __align__(256) __half2 g_h0h[(size_t)NN * 32]; // fp16 anchor (unscaled h0)
__device__ __align__(256) float g_hF[(size_t)NN * HID];   // final fp32 h
__device__ __align__(256) __half2 g_hsA[(size_t)NN * 32]; // scaled fp16 state
__device__ __align__(256) __half2 g_hsB[(size_t)NN * 32];

// ---------------- CSR build ----------------
__global__ void k_hist(const int* __restrict__ col, int e) {
    int i4 = (blockIdx.x * blockDim.x + threadIdx.x) * 4;
    if (i4 + 4 <= e) {
        int4 c = *(const int4*)(col + i4);
        atomicAdd(&g_count[c.x], 1);
        atomicAdd(&g_count[c.y], 1);
        atomicAdd(&g_count[c.z], 1);
        atomicAdd(&g_count[c.w], 1);
    } else {
        for (int i = i4; i < e; i++) atomicAdd(&g_count[col[i]], 1);
    }
}

// Hillis-Steele block scan (1024/block); also computes g_dis
__global__ void k_scan_block(int n) {
    __shared__ int s[1024];
    int i = blockIdx.x * 1024 + threadIdx.x;
    int v = (i < n) ? g_count[i] : 0;
    if (i < n) g_dis[i] = rsqrtf((float)(v + 1));  // +1 self loop
    s[threadIdx.x] = v;
    __syncthreads();
    #pragma unroll
    for (int off = 1; off < 1024; off <<= 1) {
        int t = (threadIdx.x >= off) ? s[threadIdx.x - off] : 0;
        __syncthreads();
        s[threadIdx.x] += t;
        __syncthreads();
    }
    if (i < n) g_incl[i] = s[threadIdx.x];
    if (threadIdx.x == 1023) g_blksum[blockIdx.x] = s[1023];
}

__global__ void k_scan_sums(int nb) {
    if (blockIdx.x == 0 && threadIdx.x == 0) {
        int acc = 0;
        for (int b = 0; b < nb; b++) { int t = g_blksum[b]; g_blksum[b] = acc; acc += t; }
    }
}

__global__ void k_finalize(int n) {
    int i = blockIdx.x * blockDim.x + threadIdx.x;
    if (i == 0) g_colptr[0] = 0;
    if (i < n) {
        int e = g_incl[i] + g_blksum[i >> 10];
        g_colptr[i + 1] = e;
        g_cursor[i] = e - g_count[i];
    }
}

__global__ void k_scatter_edges(const int* __restrict__ row, const int* __restrict__ col, int e) {
    int i = blockIdx.x * blockDim.x + threadIdx.x;
    if (i >= e) return;
    int c = col[i];
    int pos = atomicAdd(&g_cursor[c], 1);
    g_edge[pos] = row[i];
}

// ---------------- W preconvert: g_Wt[n][k] = (half)W[k][n] ----------------
__global__ void k_wconv(const float* __restrict__ W) {
    int i = blockIdx.x * blockDim.x + threadIdx.x;
    if (i < FIN * HID) {
        int k = i >> 6, nn = i & 63;
        g_Wt[(size_t)nn * FIN + k] = __float2half(W[(size_t)k * HID + nn]);
    }
}

// ---------------- Embed GEMM: fused fp32->fp16 reg-staged, double-buffered ------
// H0 = relu(X @ W + b). X loaded fp32 via LDG.128, converted to fp16 in
// registers (rn, bit-identical to the old preconvert pass), stored STS.128
// into the fp16 double buffer while MMA consumes the other stage.
#define KC 32
#define XSTR 40            // smem row stride in halves (80 B, 16B-aligned rows)
#define NCHUNK (FIN / KC)  // 16
__global__ __launch_bounds__(256) void k_embed_mma(const float* __restrict__ X,
                                                   const float* __restrict__ b, int n) {
    __shared__ __align__(16) __half Xs[2][128][XSTR];   // 20.5 KB
    __shared__ __align__(16) __half Ws[2][64][XSTR];    // 10.2 KB
    __shared__ float bs[HID];
    int tid = threadIdx.x;
    int wid = tid >> 5, lane = tid & 31;
    int g  = lane >> 2;          // 0..7
    int cq = (lane & 3) * 2;     // 0,2,4,6
    int rowBase = blockIdx.x * 128;
    if (tid < HID) bs[tid] = b[tid];

    // X: 2 threads/row, 16 consecutive floats each (4x LDG.128)
    int xr = tid >> 1;
    int xp = (tid & 1) * 16;     // in halves == in floats here (16 elems)
    int gxr = rowBase + xr;
    if (gxr >= n) gxr = n - 1;   // clamp; epilogue guards writes
    const float4* xsrc = (const float4*)(X + (size_t)gxr * FIN + xp);
    // W: 4 threads/row, 8 halves each (1x LDG.128)
    int wr = tid >> 2;
    int wq = (tid & 3) * 8;
    const uint4* wsrc = (const uint4*)(g_Wt + (size_t)wr * FIN + wq);

    float acc[8][4];
    #pragma unroll
    for (int i = 0; i < 8; i++)
        #pragma unroll
        for (int j = 0; j < 4; j++) acc[i][j] = 0.f;

    // prologue: chunk 0 into registers
    float4 xv[4];
    uint4  wv;
    #pragma unroll
    for (int t = 0; t < 4; t++) xv[t] = xsrc[t];
    wv = wsrc[0];

    for (int c = 0; c < NCHUNK; c++) {
        int st = c & 1;
        // convert + store current chunk into stage st (2x STS.128 for X, 1x for W)
        {
            __half2 h0 = __floats2half2_rn(xv[0].x, xv[0].y);
            __half2 h1 = __floats2half2_rn(xv[0].z, xv[0].w);
            __half2 h2 = __floats2half2_rn(xv[1].x, xv[1].y);
            __half2 h3 = __floats2half2_rn(xv[1].z, xv[1].w);
            __half2 h4 = __floats2half2_rn(xv[2].x, xv[2].y);
            __half2 h5 = __floats2half2_rn(xv[2].z, xv[2].w);
            __half2 h6 = __floats2half2_rn(xv[3].x, xv[3].y);
            __half2 h7 = __floats2half2_rn(xv[3].z, xv[3].w);
            uint4 p0, p1;
            p0.x = *(unsigned*)&h0; p0.y = *(unsigned*)&h1;
            p0.z = *(unsigned*)&h2; p0.w = *(unsigned*)&h3;
            p1.x = *(unsigned*)&h4; p1.y = *(unsigned*)&h5;
            p1.z = *(unsigned*)&h6; p1.w = *(unsigned*)&h7;
            *(uint4*)&Xs[st][xr][xp]     = p0;
            *(uint4*)&Xs[st][xr][xp + 8] = p1;
            *(uint4*)&Ws[st][wr][wq]     = wv;
        }
        __syncthreads();
        // issue next chunk's global loads (latency hidden behind MMA below)
        if (c + 1 < NCHUNK) {
            const float4* xn = xsrc + (c + 1) * (KC / 4);
            #pragma unroll
            for (int t = 0; t < 4; t++) xv[t] = xn[t];
            wv = wsrc[(c + 1) * (KC / 8)];
        }
        // MMA on stage st
        #pragma unroll
        for (int kk = 0; kk < KC; kk += 16) {
            unsigned a0 = *(const unsigned*)&Xs[st][wid * 16 + g][kk + cq];
            unsigned a1 = *(const unsigned*)&Xs[st][wid * 16 + g + 8][kk + cq];
            unsigned a2 = *(const unsigned*)&Xs[st][wid * 16 + g][kk + cq + 8];
            unsigned a3 = *(const unsigned*)&Xs[st][wid * 16 + g + 8][kk + cq + 8];
            #pragma unroll
            for (int cb = 0; cb < 8; cb++) {
                unsigned b0 = *(const unsigned*)&Ws[st][cb * 8 + g][kk + cq];
                unsigned b1 = *(const unsigned*)&Ws[st][cb * 8 + g][kk + cq + 8];
                asm volatile(
                    "mma.sync.aligned.m16n8k16.row.col.f32.f16.f16.f32 "
                    "{%0,%1,%2,%3}, {%4,%5,%6,%7}, {%8,%9}, {%0,%1,%2,%3};"
                    : "+f"(acc[cb][0]), "+f"(acc[cb][1]),
                      "+f"(acc[cb][2]), "+f"(acc[cb][3])
                    : "r"(a0), "r"(a1), "r"(a2), "r"(a3), "r"(b0), "r"(b1));
            }
        }
        __syncthreads();
    }

    // epilogue: bias + relu -> fp16 anchor g_h0h and dis-scaled fp16 state g_hsA
    int r0 = rowBase + wid * 16 + g;
    int r1 = r0 + 8;
    float d0 = (r0 < n) ? g_dis[r0] : 0.f;
    float d1 = (r1 < n) ? g_dis[r1] : 0.f;
    #pragma unroll
    for (int cb = 0; cb < 8; cb++) {
        int c = cb * 8 + cq;
        float bx = bs[c], by = bs[c + 1];
        if (r0 < n) {
            float v0 = fmaxf(acc[cb][0] + bx, 0.f);
            float v1 = fmaxf(acc[cb][1] + by, 0.f);
            g_h0h[(size_t)r0 * 32 + (c >> 1)] = __floats2half2_rn(v0, v1);
            g_hsA[(size_t)r0 * 32 + (c >> 1)] = __floats2half2_rn(d0 * v0, d0 * v1);
        }
        if (r1 < n) {
            float v0 = fmaxf(acc[cb][2] + bx, 0.f);
            float v1 = fmaxf(acc[cb][3] + by, 0.f);
            g_h0h[(size_t)r1 * 32 + (c >> 1)] = __floats2half2_rn(v0, v1);
            g_hsA[(size_t)r1 * 32 + (c >> 1)] = __floats2half2_rn(d1 * v0, d1 * v1);
        }
    }
}

// ---------------- Propagation hop: pair-split half-warp gathers (R7 known-good) --
__device__ __forceinline__ void acc4(float& a0, float& a1, float& a2, float& a3, uint2 v) {
    float2 fl = __half22float2(*(__half2*)&v.x);
    float2 fh = __half22float2(*(__half2*)&v.y);
    a0 += fl.x; a1 += fl.y; a2 += fh.x; a3 += fh.y;
}

__global__ __launch_bounds__(256) void k_hop(const uint2* __restrict__ hs,
                                             uint2* __restrict__ hn,
                                             int n, int final_hop) {
    int warp = (blockIdx.x * blockDim.x + threadIdx.x) >> 5;
    int lane = threadIdx.x & 31;
    if (warp >= n) return;
    int half = lane >> 4;      // 0 or 1
    int sub  = lane & 15;      // feature group: 4 features each
    int beg = g_colptr[warp], end = g_colptr[warp + 1];

    float a0, a1, a2, a3;
    float b0 = 0.f, b1 = 0.f, b2 = 0.f, b3 = 0.f;
    if (half == 0) {           // self loop counted once
        uint2 s = hs[(size_t)warp * 16 + sub];
        float2 fl = __half22float2(*(__half2*)&s.x);
        float2 fh = __half22float2(*(__half2*)&s.y);
        a0 = fl.x; a1 = fl.y; a2 = fh.x; a3 = fh.y;
    } else {
        a0 = a1 = a2 = a3 = 0.f;
    }

    int e = beg;
    for (; e + 8 <= end; e += 8) {    // 4 pairs = 8 edges per iteration
        int i0 = __ldg(&g_edge[e     + half]);
        int i1 = __ldg(&g_edge[e + 2 + half]);
        int i2 = __ldg(&g_edge[e + 4 + half]);
        int i3 = __ldg(&g_edge[e + 6 + half]);
        uint2 v0 = hs[(size_t)i0 * 16 + sub];
        uint2 v1 = hs[(size_t)i1 * 16 + sub];
        uint2 v2 = hs[(size_t)i2 * 16 + sub];
        uint2 v3 = hs[(size_t)i3 * 16 + sub];
        acc4(a0, a1, a2, a3, v0);
        acc4(b0, b1, b2, b3, v1);
        acc4(a0, a1, a2, a3, v2);
        acc4(b0, b1, b2, b3, v3);
    }
    for (; e + 2 <= end; e += 2) {    // single pair
        int i0 = __ldg(&g_edge[e + half]);
        uint2 v0 = hs[(size_t)i0 * 16 + sub];
        acc4(a0, a1, a2, a3, v0);
    }
    if (e < end && half == 0) {       // odd tail edge: half 0 only
        int i0 = __ldg(&g_edge[e]);
        uint2 v0 = hs[(size_t)i0 * 16 + sub];
        acc4(a0, a1, a2, a3, v0);
    }
    a0 += b0; a1 += b1; a2 += b2; a3 += b3;
    a0 += __shfl_xor_sync(0xffffffffu, a0, 16);
    a1 += __shfl_xor_sync(0xffffffffu, a1, 16);
    a2 += __shfl_xor_sync(0xffffffffu, a2, 16);
    a3 += __shfl_xor_sync(0xffffffffu, a3, 16);

    float d = g_dis[warp];
    uint2 hz = *(const uint2*)(g_h0h + (size_t)warp * 32 + sub * 2);
    float2 zl = __half22float2(*(__half2*)&hz.x);
    float2 zh = __half22float2(*(__half2*)&hz.y);
    float o0 = 0.9f * d * a0 + 0.1f * zl.x;
    float o1 = 0.9f * d * a1 + 0.1f * zl.y;
    float o2 = 0.9f * d * a2 + 0.1f * zh.x;
    float o3 = 0.9f * d * a3 + 0.1f * zh.y;

    if (half == 0) {
        if (final_hop) {
            *(float4*)(g_hF + (size_t)warp * HID + sub * 4) = make_float4(o0, o1, o2, o3);
        } else {
            __half2 p0 = __floats2half2_rn(d * o0, d * o1);
            __half2 p1 = __floats2half2_rn(d * o2, d * o3);
            uint2 w;
            w.x = *(unsigned*)&p0;
            w.y = *(unsigned*)&p1;
            hn[(size_t)warp * 16 + sub] = w;
        }
    }
}

// ---------------- Predict + softmax family ----------------
__global__ __launch_bounds__(256) void k_pred(const float* __restrict__ h,
                                              const float* __restrict__ Wp,
                                              const float* __restrict__ bp,
                                              float* __restrict__ out,
                                              int n, int out_size) {
    __shared__ float Ws[HID * NCLS];
    __shared__ float bs[NCLS];
    __shared__ float hsm[8][HID];
    for (int i = threadIdx.x; i < HID * NCLS; i += blockDim.x) Ws[i] = Wp[i];
    if (threadIdx.x < NCLS) bs[threadIdx.x] = bp[threadIdx.x];
    __syncthreads();

    int warp = threadIdx.x >> 5;
    int lane = threadIdx.x & 31;
    int v = blockIdx.x * 8 + warp;
    if (v >= n) return;

    hsm[warp][lane]      = h[(size_t)v * HID + lane];
    hsm[warp][lane + 32] = h[(size_t)v * HID + lane + 32];
    __syncwarp();

    int c1 = (lane + 32 < NCLS) ? (lane + 32) : (NCLS - 1);
    float a0 = bs[lane];
    float a1 = bs[c1];
    #pragma unroll
    for (int k = 0; k < HID; k++) {
        float hk = hsm[warp][k];
        a0 += hk * Ws[k * NCLS + lane];
        a1 += hk * Ws[k * NCLS + c1];
    }
    bool l1 = (lane + 32 < NCLS);

    float m = fmaxf(a0, l1 ? a1 : -INFINITY);
    #pragma unroll
    for (int o = 16; o > 0; o >>= 1) m = fmaxf(m, __shfl_xor_sync(0xffffffff, m, o));
    float e0 = __expf(a0 - m);
    float e1 = l1 ? __expf(a1 - m) : 0.f;
    float s = e0 + e1;
    #pragma unroll
    for (int o = 16; o > 0; o >>= 1) s += __shfl_xor_sync(0xffffffff, s, o);
    float lse = m + logf(s);
    float inv = 1.f / s;

    size_t base = (size_t)v * NCLS;
    size_t sec  = (size_t)n * NCLS;
    out[base + lane] = a0 - lse;
    if (l1) out[base + lane + 32] = a1 - lse;
    if (out_size >= 2 * (int)sec) {
        out[sec + base + lane] = a0;
        if (l1) out[sec + base + lane + 32] = a1;
    }
    if (out_size >= 3 * (int)sec) {
        out[2 * sec + base + lane] = e0 * inv;
        if (l1) out[2 * sec + base + lane + 32] = e1 * inv;
    }
}

// ---------------- launch ----------------
extern "C" void kernel_launch(void* const* d_in, const int* in_sizes, int n_in,
                              void* d_out, int out_size) {
    const float* x     = (const float*)d_in[0];   // [N,512]
    const int*   eidx  = (const int*)d_in[1];     // [2,E]
    const float* Wemb  = (const float*)d_in[2];   // [512,64]
    const float* bemb  = (const float*)d_in[3];   // [64]
    const float* Wpred = (const float*)d_in[4];   // [64,47]
    const float* bpred = (const float*)d_in[5];   // [47]
    float* out = (float*)d_out;

    int n = in_sizes[0] / FIN;
    int e = in_sizes[1] / 2;
    const int* row = eidx;       // source
    const int* col = eidx + e;   // target

    int nbE  = (e + 255) / 256;
    int nbE4 = (e / 4 + 255) / 256 + 1;
    int nbS  = (n + 1023) / 1024;

    cudaStream_t s2;
    cudaStreamCreate(&s2);
    cudaEvent_t evFork, evDis, evEmb;
    cudaEventCreateWithFlags(&evFork, cudaEventDisableTiming);
    cudaEventCreateWithFlags(&evDis,  cudaEventDisableTiming);
    cudaEventCreateWithFlags(&evEmb,  cudaEventDisableTiming);
    cudaStream_t s0 = (cudaStream_t)0;

    // fork: side stream converts W (depends only on inputs)
    cudaEventRecord(evFork, s0);
    cudaStreamWaitEvent(s2, evFork, 0);
    k_wconv<<<(FIN * HID + 255) / 256, 256, 0, s2>>>(Wemb);

    // main: degree histogram + scan (produces g_dis)
    {
        void* cntp; cudaGetSymbolAddress(&cntp, g_count);
        cudaMemsetAsync(cntp, 0, (size_t)n * sizeof(int), s0);
    }
    k_hist<<<nbE4, 256>>>(col, e);
    k_scan_block<<<nbS, 1024>>>(n);   // also computes g_dis
    cudaEventRecord(evDis, s0);

    // side: embed GEMM (needs g_dis + converted W; reads fp32 X, converts in-kernel)
    cudaStreamWaitEvent(s2, evDis, 0);
    k_embed_mma<<<(n + 127) / 128, 256, 0, s2>>>(x, bemb, n);
    cudaEventRecord(evEmb, s2);

    // main (overlapping with embed): finish CSR build
    k_scan_sums<<<1, 32>>>(nbS);
    k_finalize<<<nbS, 1024>>>(n);
    k_scatter_edges<<<nbE, 256>>>(row, col, e);

    // join
    cudaStreamWaitEvent(s0, evEmb, 0);

    // --- 10 propagation hops (ping-pong fp16 scaled state) ---
    int hopBlocks = (n * 32 + 255) / 256;
    {
        uint2* hAp; cudaGetSymbolAddress((void**)&hAp, g_hsA);
        uint2* hBp; cudaGetSymbolAddress((void**)&hBp, g_hsB);
        uint2* cur = hAp;
        for (int i = 0; i < KHOPS; i++) {
            int fin = (i == KHOPS - 1);
            uint2* dst = (cur == hAp) ? hBp : hAp;
            k_hop<<<hopBlocks, 256>>>(cur, dst, n, fin);
            cur = dst;
        }
    }

    // --- predict + softmax family (reads fp32 g_hF) ---
    float* hFp; cudaGetSymbolAddress((void**)&hFp, g_hF);
    k_pred<<<(n + 7) / 8, 256>>>(hFp, Wpred, bpred, out, n, out_size);
}

// round 12
// speedup vs baseline: 1.2180x; 1.0719x over previous
#include <cuda_runtime.h>
#include <cuda_bf16.h>
#include <cuda_fp16.h>
#include <math.h>

// Problem constants (shapes are fixed for this problem instance)
#define NN      100000
#define NE      3200000
#define FIN     512
#define HID     64
#define NCLS    47
#define KHOPS   10
#define ALPHA   0.1f

// -------- device scratch (no allocations allowed) --------
__device__ int   g_count[NN];        // in-degree counts (real edges only)
__device__ int   g_colptr[NN + 1];   // CSR row pointers (by destination)
__device__ int   g_cursor[NN];       // scatter cursors
__device__ float g_dis[NN];          // D^-1/2 (deg incl. self loop)
__device__ int   g_incl[NN];         // inclusive per-block scan temp
__device__ int   g_blksum[256];      // block sums for scan
__device__ __align__(16) int g_edge[NE + 8];  // src index, sorted by dst (+pad)
__device__ __half g_Wt[(size_t)HID * FIN];                // W^T fp16 [64][512]
__device__ __align__(256) __half2 g_h0h[(size_t)NN * 32]; // fp16 anchor (unscaled h0)
__device__ __align__(256) float g_hF[(size_t)NN * HID];   // final fp32 h
__device__ __align__(256) __half2 g_hsA[(size_t)NN * 32]; // scaled fp16 state
__device__ __align__(256) __half2 g_hsB[(size_t)NN * 32];

// ---------------- CSR build ----------------
__global__ void k_hist(const int* __restrict__ col, int e) {
    int i4 = (blockIdx.x * blockDim.x + threadIdx.x) * 4;
    if (i4 + 4 <= e) {
        int4 c = *(const int4*)(col + i4);
        atomicAdd(&g_count[c.x], 1);
        atomicAdd(&g_count[c.y], 1);
        atomicAdd(&g_count[c.z], 1);
        atomicAdd(&g_count[c.w], 1);
    } else {
        for (int i = i4; i < e; i++) atomicAdd(&g_count[col[i]], 1);
    }
}

// Hillis-Steele block scan (1024/block); also computes g_dis
__global__ void k_scan_block(int n) {
    __shared__ int s[1024];
    int i = blockIdx.x * 1024 + threadIdx.x;
    int v = (i < n) ? g_count[i] : 0;
    if (i < n) g_dis[i] = rsqrtf((float)(v + 1));  // +1 self loop
    s[threadIdx.x] = v;
    __syncthreads();
    #pragma unroll
    for (int off = 1; off < 1024; off <<= 1) {
        int t = (threadIdx.x >= off) ? s[threadIdx.x - off] : 0;
        __syncthreads();
        s[threadIdx.x] += t;
        __syncthreads();
    }
    if (i < n) g_incl[i] = s[threadIdx.x];
    if (threadIdx.x == 1023) g_blksum[blockIdx.x] = s[1023];
}

// warp-parallel exclusive scan of block sums (shfl scan, chunks of 32)
__global__ void k_scan_sums(int nb) {
    int lane = threadIdx.x & 31;
    int carry = 0;
    for (int base = 0; base < nb; base += 32) {
        int i = base + lane;
        int orig = (i < nb) ? g_blksum[i] : 0;
        int v = orig;
        #pragma unroll
        for (int off = 1; off < 32; off <<= 1) {
            int t = __shfl_up_sync(0xffffffffu, v, off);
            if (lane >= off) v += t;
        }
        if (i < nb) g_blksum[i] = (v - orig) + carry;   // exclusive + carry
        carry += __shfl_sync(0xffffffffu, v, 31);       // chunk total
    }
}

__global__ void k_finalize(int n) {
    int i = blockIdx.x * blockDim.x + threadIdx.x;
    if (i == 0) g_colptr[0] = 0;
    if (i < n) {
        int e = g_incl[i] + g_blksum[i >> 10];
        g_colptr[i + 1] = e;
        g_cursor[i] = e - g_count[i];
    }
}

__global__ void k_scatter_edges(const int* __restrict__ row, const int* __restrict__ col, int e) {
    int i = blockIdx.x * blockDim.x + threadIdx.x;
    if (i >= e) return;
    int c = col[i];
    int pos = atomicAdd(&g_cursor[c], 1);
    g_edge[pos] = row[i];
}

// ---------------- W preconvert: g_Wt[n][k] = (half)W[k][n] ----------------
__global__ void k_wconv(const float* __restrict__ W) {
    int i = blockIdx.x * blockDim.x + threadIdx.x;
    if (i < FIN * HID) {
        int k = i >> 6, nn = i & 63;
        g_Wt[(size_t)nn * FIN + k] = __float2half(W[(size_t)k * HID + nn]);
    }
}

// ---------------- Embed GEMM: fused fp32->fp16 reg-staged, double-buffered ------
#define KC 32
#define XSTR 40            // smem row stride in halves (80 B, 16B-aligned rows)
#define NCHUNK (FIN / KC)  // 16
__global__ __launch_bounds__(256, 3) void k_embed_mma(const float* __restrict__ X,
                                                      const float* __restrict__ b, int n) {
    __shared__ __align__(16) __half Xs[2][128][XSTR];   // 20.5 KB
    __shared__ __align__(16) __half Ws[2][64][XSTR];    // 10.2 KB
    __shared__ float bs[HID];
    int tid = threadIdx.x;
    int wid = tid >> 5, lane = tid & 31;
    int g  = lane >> 2;          // 0..7
    int cq = (lane & 3) * 2;     // 0,2,4,6
    int rowBase = blockIdx.x * 128;
    if (tid < HID) bs[tid] = b[tid];

    // X: 2 threads/row, 16 consecutive floats each (4x LDG.128)
    int xr = tid >> 1;
    int xp = (tid & 1) * 16;
    int gxr = rowBase + xr;
    if (gxr >= n) gxr = n - 1;   // clamp; epilogue guards writes
    const float4* xsrc = (const float4*)(X + (size_t)gxr * FIN + xp);
    // W: 4 threads/row, 8 halves each (1x LDG.128)
    int wr = tid >> 2;
    int wq = (tid & 3) * 8;
    const uint4* wsrc = (const uint4*)(g_Wt + (size_t)wr * FIN + wq);

    float acc[8][4];
    #pragma unroll
    for (int i = 0; i < 8; i++)
        #pragma unroll
        for (int j = 0; j < 4; j++) acc[i][j] = 0.f;

    float4 xv[4];
    uint4  wv;
    #pragma unroll
    for (int t = 0; t < 4; t++) xv[t] = xsrc[t];
    wv = wsrc[0];

    for (int c = 0; c < NCHUNK; c++) {
        int st = c & 1;
        {
            __half2 h0 = __floats2half2_rn(xv[0].x, xv[0].y);
            __half2 h1 = __floats2half2_rn(xv[0].z, xv[0].w);
            __half2 h2 = __floats2half2_rn(xv[1].x, xv[1].y);
            __half2 h3 = __floats2half2_rn(xv[1].z, xv[1].w);
            __half2 h4 = __floats2half2_rn(xv[2].x, xv[2].y);
            __half2 h5 = __floats2half2_rn(xv[2].z, xv[2].w);
            __half2 h6 = __floats2half2_rn(xv[3].x, xv[3].y);
            __half2 h7 = __floats2half2_rn(xv[3].z, xv[3].w);
            uint4 p0, p1;
            p0.x = *(unsigned*)&h0; p0.y = *(unsigned*)&h1;
            p0.z = *(unsigned*)&h2; p0.w = *(unsigned*)&h3;
            p1.x = *(unsigned*)&h4; p1.y = *(unsigned*)&h5;
            p1.z = *(unsigned*)&h6; p1.w = *(unsigned*)&h7;
            *(uint4*)&Xs[st][xr][xp]     = p0;
            *(uint4*)&Xs[st][xr][xp + 8] = p1;
            *(uint4*)&Ws[st][wr][wq]     = wv;
        }
        __syncthreads();
        if (c + 1 < NCHUNK) {
            const float4* xn = xsrc + (c + 1) * (KC / 4);
            #pragma unroll
            for (int t = 0; t < 4; t++) xv[t] = xn[t];
            wv = wsrc[(c + 1) * (KC / 8)];
        }
        #pragma unroll
        for (int kk = 0; kk < KC; kk += 16) {
            unsigned a0 = *(const unsigned*)&Xs[st][wid * 16 + g][kk + cq];
            unsigned a1 = *(const unsigned*)&Xs[st][wid * 16 + g + 8][kk + cq];
            unsigned a2 = *(const unsigned*)&Xs[st][wid * 16 + g][kk + cq + 8];
            unsigned a3 = *(const unsigned*)&Xs[st][wid * 16 + g + 8][kk + cq + 8];
            #pragma unroll
            for (int cb = 0; cb < 8; cb++) {
                unsigned b0 = *(const unsigned*)&Ws[st][cb * 8 + g][kk + cq];
                unsigned b1 = *(const unsigned*)&Ws[st][cb * 8 + g][kk + cq + 8];
                asm volatile(
                    "mma.sync.aligned.m16n8k16.row.col.f32.f16.f16.f32 "
                    "{%0,%1,%2,%3}, {%4,%5,%6,%7}, {%8,%9}, {%0,%1,%2,%3};"
                    : "+f"(acc[cb][0]), "+f"(acc[cb][1]),
                      "+f"(acc[cb][2]), "+f"(acc[cb][3])
                    : "r"(a0), "r"(a1), "r"(a2), "r"(a3), "r"(b0), "r"(b1));
            }
        }
        __syncthreads();
    }

    // epilogue: bias + relu -> fp16 anchor g_h0h and dis-scaled fp16 state g_hsA
    int r0 = rowBase + wid * 16 + g;
    int r1 = r0 + 8;
    float d0 = (r0 < n) ? g_dis[r0] : 0.f;
    float d1 = (r1 < n) ? g_dis[r1] : 0.f;
    #pragma unroll
    for (int cb = 0; cb < 8; cb++) {
        int c = cb * 8 + cq;
        float bx = bs[c], by = bs[c + 1];
        if (r0 < n) {
            float v0 = fmaxf(acc[cb][0] + bx, 0.f);
            float v1 = fmaxf(acc[cb][1] + by, 0.f);
            g_h0h[(size_t)r0 * 32 + (c >> 1)] = __floats2half2_rn(v0, v1);
            g_hsA[(size_t)r0 * 32 + (c >> 1)] = __floats2half2_rn(d0 * v0, d0 * v1);
        }
        if (r1 < n) {
            float v0 = fmaxf(acc[cb][2] + bx, 0.f);
            float v1 = fmaxf(acc[cb][3] + by, 0.f);
            g_h0h[(size_t)r1 * 32 + (c >> 1)] = __floats2half2_rn(v0, v1);
            g_hsA[(size_t)r1 * 32 + (c >> 1)] = __floats2half2_rn(d1 * v0, d1 * v1);
        }
    }
}

// ---------------- Propagation hop: pair-split half-warp gathers (known-good) ----
__device__ __forceinline__ void acc4(float& a0, float& a1, float& a2, float& a3, uint2 v) {
    float2 fl = __half22float2(*(__half2*)&v.x);
    float2 fh = __half22float2(*(__half2*)&v.y);
    a0 += fl.x; a1 += fl.y; a2 += fh.x; a3 += fh.y;
}

__global__ __launch_bounds__(256) void k_hop(const uint2* __restrict__ hs,
                                             uint2* __restrict__ hn,
                                             int n, int final_hop) {
    int warp = (blockIdx.x * blockDim.x + threadIdx.x) >> 5;
    int lane = threadIdx.x & 31;
    if (warp >= n) return;
    int half = lane >> 4;      // 0 or 1
    int sub  = lane & 15;      // feature group: 4 features each
    int beg = g_colptr[warp], end = g_colptr[warp + 1];

    float a0, a1, a2, a3;
    float b0 = 0.f, b1 = 0.f, b2 = 0.f, b3 = 0.f;
    if (half == 0) {           // self loop counted once
        uint2 s = hs[(size_t)warp * 16 + sub];
        float2 fl = __half22float2(*(__half2*)&s.x);
        float2 fh = __half22float2(*(__half2*)&s.y);
        a0 = fl.x; a1 = fl.y; a2 = fh.x; a3 = fh.y;
    } else {
        a0 = a1 = a2 = a3 = 0.f;
    }

    int e = beg;
    for (; e + 8 <= end; e += 8) {
        int i0 = __ldg(&g_edge[e     + half]);
        int i1 = __ldg(&g_edge[e + 2 + half]);
        int i2 = __ldg(&g_edge[e + 4 + half]);
        int i3 = __ldg(&g_edge[e + 6 + half]);
        uint2 v0 = hs[(size_t)i0 * 16 + sub];
        uint2 v1 = hs[(size_t)i1 * 16 + sub];
        uint2 v2 = hs[(size_t)i2 * 16 + sub];
        uint2 v3 = hs[(size_t)i3 * 16 + sub];
        acc4(a0, a1, a2, a3, v0);
        acc4(b0, b1, b2, b3, v1);
        acc4(a0, a1, a2, a3, v2);
        acc4(b0, b1, b2, b3, v3);
    }
    for (; e + 2 <= end; e += 2) {
        int i0 = __ldg(&g_edge[e + half]);
        uint2 v0 = hs[(size_t)i0 * 16 + sub];
        acc4(a0, a1, a2, a3, v0);
    }
    if (e < end && half == 0) {
        int i0 = __ldg(&g_edge[e]);
        uint2 v0 = hs[(size_t)i0 * 16 + sub];
        acc4(a0, a1, a2, a3, v0);
    }
    a0 += b0; a1 += b1; a2 += b2; a3 += b3;
    a0 += __shfl_xor_sync(0xffffffffu, a0, 16);
    a1 += __shfl_xor_sync(0xffffffffu, a1, 16);
    a2 += __shfl_xor_sync(0xffffffffu, a2, 16);
    a3 += __shfl_xor_sync(0xffffffffu, a3, 16);

    float d = g_dis[warp];
    uint2 hz = *(const uint2*)(g_h0h + (size_t)warp * 32 + sub * 2);
    float2 zl = __half22float2(*(__half2*)&hz.x);
    float2 zh = __half22float2(*(__half2*)&hz.y);
    float o0 = 0.9f * d * a0 + 0.1f * zl.x;
    float o1 = 0.9f * d * a1 + 0.1f * zl.y;
    float o2 = 0.9f * d * a2 + 0.1f * zh.x;
    float o3 = 0.9f * d * a3 + 0.1f * zh.y;

    if (half == 0) {
        if (final_hop) {
            *(float4*)(g_hF + (size_t)warp * HID + sub * 4) = make_float4(o0, o1, o2, o3);
        } else {
            __half2 p0 = __floats2half2_rn(d * o0, d * o1);
            __half2 p1 = __floats2half2_rn(d * o2, d * o3);
            uint2 w;
            w.x = *(unsigned*)&p0;
            w.y = *(unsigned*)&p1;
            hn[(size_t)warp * 16 + sub] = w;
        }
    }
}

// ---------------- Predict + softmax family: 4 nodes/warp, k-outer ----------------
__global__ __launch_bounds__(256) void k_pred(const float* __restrict__ h,
                                              const float* __restrict__ Wp,
                                              const float* __restrict__ bp,
                                              float* __restrict__ out,
                                              int n, int out_size) {
    __shared__ __align__(16) float Ws[HID * NCLS];     // 12 KB
    __shared__ __align__(16) float bs[48];             // padded
    __shared__ __align__(16) float hsm[8][4][HID];     // 8 KB, 16B aligned
    for (int i = threadIdx.x; i < HID * NCLS; i += blockDim.x) Ws[i] = Wp[i];
    if (threadIdx.x < NCLS) bs[threadIdx.x] = bp[threadIdx.x];
    __syncthreads();

    int warp = threadIdx.x >> 5;
    int lane = threadIdx.x & 31;
    int vBase = blockIdx.x * 32 + warp * 4;
    if (vBase >= n) return;

    // load 4 node rows (256 consecutive floats) coalesced: 2x float4 per lane
    #pragma unroll
    for (int t = 0; t < 2; t++) {
        int f = lane * 8 + t * 4;       // 0..255, 16B aligned
        int j = f >> 6;
        int k = f & 63;
        int v = vBase + j;
        if (v >= n) v = n - 1;
        float4 val = *(const float4*)(h + (size_t)v * HID + k);
        *(float4*)&hsm[warp][j][k] = val;
    }
    __syncwarp();

    bool l1 = (lane + 32 < NCLS);
    int c1 = l1 ? (lane + 32) : (NCLS - 1);
    float acc0[4], acc1[4];
    #pragma unroll
    for (int j = 0; j < 4; j++) { acc0[j] = bs[lane]; acc1[j] = bs[c1]; }

    #pragma unroll 8
    for (int k = 0; k < HID; k++) {
        float w0 = Ws[k * NCLS + lane];
        float w1 = Ws[k * NCLS + c1];
        #pragma unroll
        for (int j = 0; j < 4; j++) {
            float hk = hsm[warp][j][k];
            acc0[j] += hk * w0;
            acc1[j] += hk * w1;
        }
    }

    size_t sec = (size_t)n * NCLS;
    #pragma unroll
    for (int j = 0; j < 4; j++) {
        int v = vBase + j;
        if (v >= n) break;
        float a0 = acc0[j], a1 = acc1[j];

        float m = fmaxf(a0, l1 ? a1 : -INFINITY);
        #pragma unroll
        for (int o = 16; o > 0; o >>= 1) m = fmaxf(m, __shfl_xor_sync(0xffffffff, m, o));
        float e0 = __expf(a0 - m);
        float e1 = l1 ? __expf(a1 - m) : 0.f;
        float s = e0 + e1;
        #pragma unroll
        for (int o = 16; o > 0; o >>= 1) s += __shfl_xor_sync(0xffffffff, s, o);
        float lse = m + logf(s);
        float inv = 1.f / s;

        size_t base = (size_t)v * NCLS;
        out[base + lane] = a0 - lse;
        if (l1) out[base + lane + 32] = a1 - lse;
        if (out_size >= 2 * (int)sec) {
            out[sec + base + lane] = a0;
            if (l1) out[sec + base + lane + 32] = a1;
        }
        if (out_size >= 3 * (int)sec) {
            out[2 * sec + base + lane] = e0 * inv;
            if (l1) out[2 * sec + base + lane + 32] = e1 * inv;
        }
    }
}

// ---------------- launch ----------------
extern "C" void kernel_launch(void* const* d_in, const int* in_sizes, int n_in,
                              void* d_out, int out_size) {
    const float* x     = (const float*)d_in[0];   // [N,512]
    const int*   eidx  = (const int*)d_in[1];     // [2,E]
    const float* Wemb  = (const float*)d_in[2];   // [512,64]
    const float* bemb  = (const float*)d_in[3];   // [64]
    const float* Wpred = (const float*)d_in[4];   // [64,47]
    const float* bpred = (const float*)d_in[5];   // [47]
    float* out = (float*)d_out;

    int n = in_sizes[0] / FIN;
    int e = in_sizes[1] / 2;
    const int* row = eidx;       // source
    const int* col = eidx + e;   // target

    int nbE  = (e + 255) / 256;
    int nbE4 = (e / 4 + 255) / 256 + 1;
    int nbS  = (n + 1023) / 1024;

    cudaStream_t s2;
    cudaStreamCreate(&s2);
    cudaEvent_t evFork, evDis, evEmb;
    cudaEventCreateWithFlags(&evFork, cudaEventDisableTiming);
    cudaEventCreateWithFlags(&evDis,  cudaEventDisableTiming);
    cudaEventCreateWithFlags(&evEmb,  cudaEventDisableTiming);
    cudaStream_t s0 = (cudaStream_t)0;

    // fork: side stream converts W (depends only on inputs)
    cudaEventRecord(evFork, s0);
    cudaStreamWaitEvent(s2, evFork, 0);
    k_wconv<<<(FIN * HID + 255) / 256, 256, 0, s2>>>(Wemb);

    // main: degree histogram + scan (produces g_dis)
    {
        void* cntp; cudaGetSymbolAddress(&cntp, g_count);
        cudaMemsetAsync(cntp, 0, (size_t)n * sizeof(int), s0);
    }
    k_hist<<<nbE4, 256>>>(col, e);
    k_scan_block<<<nbS, 1024>>>(n);   // also computes g_dis
    cudaEventRecord(evDis, s0);

    // side: embed GEMM (needs g_dis + converted W; reads fp32 X, converts in-kernel)
    cudaStreamWaitEvent(s2, evDis, 0);
    k_embed_mma<<<(n + 127) / 128, 256, 0, s2>>>(x, bemb, n);
    cudaEventRecord(evEmb, s2);

    // main (overlapping with embed): finish CSR build
    k_scan_sums<<<1, 32>>>(nbS);
    k_finalize<<<nbS, 1024>>>(n);
    k_scatter_edges<<<nbE, 256>>>(row, col, e);

    // join
    cudaStreamWaitEvent(s0, evEmb, 0);

    // --- 10 propagation hops (ping-pong fp16 scaled state) ---
    int hopBlocks = (n * 32 + 255) / 256;
    {
        uint2* hAp; cudaGetSymbolAddress((void**)&hAp, g_hsA);
        uint2* hBp; cudaGetSymbolAddress((void**)&hBp, g_hsB);
        uint2* cur = hAp;
        for (int i = 0; i < KHOPS; i++) {
            int fin = (i == KHOPS - 1);
            uint2* dst = (cur == hAp) ? hBp : hAp;
            k_hop<<<hopBlocks, 256>>>(cur, dst, n, fin);
            cur = dst;
        }
    }

    // --- predict + softmax family (reads fp32 g_hF) ---
    float* hFp; cudaGetSymbolAddress((void**)&hFp, g_hF);
    k_pred<<<(n + 31) / 32, 256>>>(hFp, Wpred, bpred, out, n, out_size);
}